// round 1
// baseline (speedup 1.0000x reference)
#include <cuda_runtime.h>
#include <math.h>

// ---------------------------------------------------------------------------
// AutoBoxGraphAttention: B=8, C=512, H=W=64, NH=8, HD=64
// Stages:
//  1) box_net:  conv3x3(512->64)+GELU -> conv1x1(64->4)+sigmoid       -> boxes
//  2) edge_net: conv3x3(4->64) -> GN(8,64)+GELU -> conv1x1(64->8)     -> edge
//  3) qkv:      conv1x1(512->1536)                                    -> qkv
//  4) attn:     per (b,h,i): S = Q^T K /8 + edge[b,h,i,w];
//               softmax over i (across slices); agg = A V^T
//  5) fusion:   conv3x3(concat(x,agg):1024->512) -> BN(train) -> SiLU -> out
// ---------------------------------------------------------------------------

#define BATCH 8
#define HW 4096   // 64*64

// ------------------------- device scratch buffers --------------------------
__device__ float g_wt_box1[4608 * 64];
__device__ float g_wt_edge1[36 * 64];
__device__ float g_wt_qkv[512 * 1536];
__device__ float g_wt_fus[9216 * 512];
__device__ float g_t1[BATCH * 64 * HW];      // box conv1 out (post-GELU)
__device__ float g_boxes[BATCH * 4 * HW];
__device__ float g_e1[BATCH * 64 * HW];      // edge conv1 out / GN in-place
__device__ float g_edge[BATCH * 8 * HW];
__device__ float g_qkv[BATCH * 1536 * HW];   // 192 MB
__device__ float g_S[BATCH * 8 * 64 * HW];   // 67 MB  S[b,h,i,w,W]
__device__ float g_fusin[BATCH * 1024 * HW]; // 128 MB concat(x, agg)
__device__ float g_y[BATCH * 512 * HW];      // fusion conv out
__device__ float g_bnmean[512];
__device__ float g_bnvar[512];

// ------------------------------ helpers ------------------------------------
__device__ __forceinline__ float gelu_exact(float v) {
    return 0.5f * v * (1.0f + erff(v * 0.70710678118654752f));
}
__device__ __forceinline__ float sigmoidf_(float v) {
    return 1.0f / (1.0f + expf(-v));
}
__device__ __forceinline__ float apply_act(float v, int act) {
    if (act == 1) return gelu_exact(v);
    if (act == 2) return sigmoidf_(v);
    return v;
}

// block reduce for 256 threads (8 warps); sh must hold >= 8 floats
__device__ __forceinline__ float block_reduce_sum_256(float v, float* sh) {
    #pragma unroll
    for (int o = 16; o; o >>= 1) v += __shfl_xor_sync(0xffffffffu, v, o);
    int w = threadIdx.x >> 5;
    if ((threadIdx.x & 31) == 0) sh[w] = v;
    __syncthreads();
    float r = 0.0f;
    if (threadIdx.x < 8) {
        r = sh[threadIdx.x];
        #pragma unroll
        for (int o = 4; o; o >>= 1) r += __shfl_xor_sync(0xffu, r, o);
    }
    if (threadIdx.x == 0) sh[0] = r;
    __syncthreads();
    float out = sh[0];
    __syncthreads();
    return out;
}

// --------------------------- weight transpose -------------------------------
// w[Cout][K] -> wt[K][Cout]
__global__ void transpose_w(const float* __restrict__ w, float* __restrict__ wt,
                            int Cout, int K) {
    __shared__ float tile[32][33];
    int k = blockIdx.x * 32 + threadIdx.x;
    int co = blockIdx.y * 32 + threadIdx.y;
    if (co < Cout && k < K) tile[threadIdx.y][threadIdx.x] = w[co * K + k];
    __syncthreads();
    int k2 = blockIdx.x * 32 + threadIdx.y;
    int co2 = blockIdx.y * 32 + threadIdx.x;
    if (k2 < K && co2 < Cout) wt[k2 * Cout + co2] = tile[threadIdx.x][threadIdx.y];
}

// ------------------------ implicit-GEMM conv (NCHW) --------------------------
// y[b, m0+m, p] = act( bias + sum_k wt[k][m0+m] * im2col(x)[k][n] )
// K index (R=3): k = ci*9 + ky*3 + kx.  N index: n = b*4096 + p, BN divides 4096.
template<int BM, int BN, int BK, int TM, int TN, int R>
__global__ void __launch_bounds__(256)
conv_kernel(const float* __restrict__ x, const float* __restrict__ wt,
            const float* __restrict__ bias, float* __restrict__ out,
            int Cin, int Cout, int act) {
    constexpr int TPB = (BM / TM) * (BN / TN);
    const int tid = threadIdx.x;
    const int Ktot = Cin * R * R;
    const int m0 = blockIdx.y * BM;
    const int n0 = blockIdx.x * BN;
    const int b = n0 >> 12;
    const int p0 = n0 & 4095;
    const int y0 = p0 >> 6;

    __shared__ float As[BK][BM];
    __shared__ float Bs[BK][BN];

    float acc[TM][TN];
    #pragma unroll
    for (int i = 0; i < TM; i++)
        #pragma unroll
        for (int j = 0; j < TN; j++) acc[i][j] = 0.0f;

    const int tn = tid % (BN / TN);
    const int tm = tid / (BN / TN);

    for (int k0 = 0; k0 < Ktot; k0 += BK) {
        // A tile: wt[K][Cout], coalesced over m
        #pragma unroll
        for (int it = 0; it < (BM * BK) / TPB; it++) {
            int i = tid + it * TPB;
            int m = i % BM, k = i / BM;
            int kk = k0 + k;
            As[k][m] = (kk < Ktot) ? wt[kk * Cout + m0 + m] : 0.0f;
        }
        // B tile: gathered im2col, coalesced over n
        #pragma unroll
        for (int it = 0; it < (BN * BK) / TPB; it++) {
            int i = tid + it * TPB;
            int n = i % BN, k = i / BN;
            int kk = k0 + k;
            float v = 0.0f;
            if (kk < Ktot) {
                int ci, sy, sx;
                if (R == 3) {
                    ci = kk / 9;
                    int r = kk - ci * 9;
                    int ky = r / 3, kx = r - ky * 3;
                    sy = y0 + (n >> 6) + ky - 1;
                    sx = (n & 63) + kx - 1;
                } else {
                    ci = kk;
                    sy = y0 + (n >> 6);
                    sx = n & 63;
                }
                if ((unsigned)sy < 64u && (unsigned)sx < 64u)
                    v = x[((b * Cin + ci) << 12) + (sy << 6) + sx];
            }
            Bs[k][n] = v;
        }
        __syncthreads();
        #pragma unroll
        for (int k = 0; k < BK; k++) {
            float a[TM], bv[TN];
            #pragma unroll
            for (int i = 0; i < TM; i += 4)
                *(float4*)&a[i] = *(const float4*)&As[k][tm * TM + i];
            #pragma unroll
            for (int j = 0; j < TN; j += 4)
                *(float4*)&bv[j] = *(const float4*)&Bs[k][tn * TN + j];
            #pragma unroll
            for (int i = 0; i < TM; i++)
                #pragma unroll
                for (int j = 0; j < TN; j++)
                    acc[i][j] += a[i] * bv[j];
        }
        __syncthreads();
    }

    #pragma unroll
    for (int i = 0; i < TM; i++) {
        int co = m0 + tm * TM + i;
        float bs = bias[co];
        float* orow = out + ((b * Cout + co) << 12) + p0 + tn * TN;
        #pragma unroll
        for (int j = 0; j < TN; j++)
            orow[j] = apply_act(acc[i][j] + bs, act);
    }
}

// ------------------------ small 1x1 conv (Cout tiny) -------------------------
template<int COUT, int CIN>
__global__ void conv1x1_small(const float* __restrict__ in, const float* __restrict__ w,
                              const float* __restrict__ bias, float* __restrict__ out,
                              int act) {
    __shared__ float ws[COUT * CIN];
    for (int i = threadIdx.x; i < COUT * CIN; i += blockDim.x) ws[i] = w[i];
    __syncthreads();
    int idx = blockIdx.x * blockDim.x + threadIdx.x; // over B*HW
    if (idx >= BATCH * HW) return;
    int b = idx >> 12, p = idx & 4095;
    float acc[COUT];
    #pragma unroll
    for (int co = 0; co < COUT; co++) acc[co] = bias[co];
    for (int ci = 0; ci < CIN; ci++) {
        float v = in[((b * CIN + ci) << 12) + p];
        #pragma unroll
        for (int co = 0; co < COUT; co++) acc[co] += ws[co * CIN + ci] * v;
    }
    #pragma unroll
    for (int co = 0; co < COUT; co++)
        out[((b * COUT + co) << 12) + p] = apply_act(acc[co], act);
}

// ---------------------- GroupNorm(8 groups of 8ch) + GELU -------------------
__global__ void groupnorm_gelu(float* __restrict__ e, const float* __restrict__ g,
                               const float* __restrict__ bta) {
    __shared__ float sh[8];
    int b = blockIdx.x >> 3, grp = blockIdx.x & 7;
    const int base = (b * 64 + grp * 8) << 12; // 8 channels * 4096
    float s = 0.0f, s2 = 0.0f;
    for (int i = threadIdx.x; i < 8 * HW; i += blockDim.x) {
        float v = e[base + i];
        s += v; s2 += v * v;
    }
    s = block_reduce_sum_256(s, sh);
    s2 = block_reduce_sum_256(s2, sh);
    float mean = s * (1.0f / 32768.0f);
    float var = s2 * (1.0f / 32768.0f) - mean * mean;
    float rstd = rsqrtf(var + 1e-5f);
    for (int i = threadIdx.x; i < 8 * HW; i += blockDim.x) {
        int ch = grp * 8 + (i >> 12);
        float v = (e[base + i] - mean) * rstd * g[ch] + bta[ch];
        e[base + i] = gelu_exact(v);
    }
}

// ---------------------- attention: S = Q^T K / 8 + edge ---------------------
__global__ void __launch_bounds__(256) qk_kernel(const float* __restrict__ qkv,
                                                 const float* __restrict__ edge,
                                                 float* __restrict__ S) {
    int blk = blockIdx.x;           // b*512 + h*64 + i
    int b = blk >> 9;
    int hi = blk & 511;
    const float* Q = qkv + ((b * 1536 + hi) << 12);
    const float* K = qkv + ((b * 1536 + 512 + hi) << 12);
    const float* E = edge + (blk << 6);

    __shared__ float Qs[64 * 64];
    __shared__ float Ks[64 * 64];
    __shared__ float Es[64];
    int tid = threadIdx.x;
    #pragma unroll
    for (int it = 0; it < 4; it++) {
        int i = tid + it * 256;
        ((float4*)Qs)[i] = ((const float4*)Q)[i];
        ((float4*)Ks)[i] = ((const float4*)K)[i];
    }
    if (tid < 64) Es[tid] = E[tid];
    __syncthreads();

    int tW = tid & 15, tw = tid >> 4;
    float acc[4][4];
    #pragma unroll
    for (int r = 0; r < 4; r++)
        #pragma unroll
        for (int c = 0; c < 4; c++) acc[r][c] = 0.0f;

    #pragma unroll 4
    for (int d = 0; d < 64; d++) {
        float4 qv = *(const float4*)&Qs[d * 64 + tw * 4];
        float4 kv = *(const float4*)&Ks[d * 64 + tW * 4];
        float qa[4] = {qv.x, qv.y, qv.z, qv.w};
        float ka[4] = {kv.x, kv.y, kv.z, kv.w};
        #pragma unroll
        for (int r = 0; r < 4; r++)
            #pragma unroll
            for (int c = 0; c < 4; c++) acc[r][c] += qa[r] * ka[c];
    }
    float* So = S + (blk << 12);
    #pragma unroll
    for (int r = 0; r < 4; r++) {
        int w = tw * 4 + r;
        float e = Es[w];
        #pragma unroll
        for (int c = 0; c < 4; c++)
            So[w * 64 + tW * 4 + c] = acc[r][c] * 0.125f + e;
    }
}

// ------------------- softmax over i (stride 4096 within bh) -----------------
__global__ void __launch_bounds__(256) softmax_i(float* __restrict__ S) {
    int col = blockIdx.x * blockDim.x + threadIdx.x; // over 8*8*4096
    if (col >= 64 * HW) return;
    int bh = col >> 12, p = col & 4095;
    float* base = S + (bh << 18) + p; // bh * 64 * 4096
    float vals[64];
    float mx = -3.0e38f;
    #pragma unroll
    for (int i = 0; i < 64; i++) {
        vals[i] = base[i << 12];
        mx = fmaxf(mx, vals[i]);
    }
    float sum = 0.0f;
    #pragma unroll
    for (int i = 0; i < 64; i++) {
        vals[i] = expf(vals[i] - mx);
        sum += vals[i];
    }
    float inv = 1.0f / sum;
    #pragma unroll
    for (int i = 0; i < 64; i++) base[i << 12] = vals[i] * inv;
}

// ---------------- agg = V A^T, write into fusin channels [512,1024) ---------
__global__ void __launch_bounds__(256) av_kernel(const float* __restrict__ S,
                                                 const float* __restrict__ qkv,
                                                 float* __restrict__ fusin) {
    int blk = blockIdx.x; // b*512 + hi
    int b = blk >> 9;
    int hi = blk & 511;
    const float* A = S + (blk << 12);                       // A[w][W]
    const float* V = qkv + ((b * 1536 + 1024 + hi) << 12);  // V[d][W]

    __shared__ float As_[64][65];
    __shared__ float Vs[64][65];
    int tid = threadIdx.x;
    #pragma unroll
    for (int it = 0; it < 16; it++) {
        int i = tid + it * 256;
        int r = i >> 6, c = i & 63;
        As_[r][c] = A[i];
        Vs[r][c] = V[i];
    }
    __syncthreads();

    int tw = tid & 15, td = tid >> 4;
    float acc[4][4]; // acc[d][w]
    #pragma unroll
    for (int r = 0; r < 4; r++)
        #pragma unroll
        for (int c = 0; c < 4; c++) acc[r][c] = 0.0f;

    #pragma unroll 4
    for (int W = 0; W < 64; W++) {
        float v[4], a[4];
        #pragma unroll
        for (int r = 0; r < 4; r++) v[r] = Vs[td * 4 + r][W];
        #pragma unroll
        for (int c = 0; c < 4; c++) a[c] = As_[tw * 4 + c][W];
        #pragma unroll
        for (int r = 0; r < 4; r++)
            #pragma unroll
            for (int c = 0; c < 4; c++) acc[r][c] += v[r] * a[c];
    }
    float* out = fusin + ((b * 1024 + 512 + hi) << 12);
    #pragma unroll
    for (int r = 0; r < 4; r++)
        #pragma unroll
        for (int c = 0; c < 4; c++)
            out[(td * 4 + r) * 64 + tw * 4 + c] = acc[r][c];
}

// ------------------- copy x into fusin channels [0,512) ---------------------
__global__ void copy_x(const float* __restrict__ x, float* __restrict__ fusin) {
    int idx = blockIdx.x * blockDim.x + threadIdx.x; // float4 over B*512*HW
    const float4* x4 = (const float4*)x;
    float4* f4 = (float4*)fusin;
    int b = idx / 524288;            // 512*4096/4
    int rem = idx - b * 524288;
    f4[b * 1048576 + rem] = x4[idx]; // 1024*4096/4
}

// ------------------------- BatchNorm stats + SiLU ---------------------------
__global__ void bn_stats(const float* __restrict__ y, float* __restrict__ mean,
                         float* __restrict__ var) {
    __shared__ float sh[8];
    int c = blockIdx.x;
    float s = 0.0f, s2 = 0.0f;
    for (int i = threadIdx.x; i < BATCH * HW; i += blockDim.x) {
        int b = i >> 12, p = i & 4095;
        float v = y[((b * 512 + c) << 12) + p];
        s += v; s2 += v * v;
    }
    s = block_reduce_sum_256(s, sh);
    s2 = block_reduce_sum_256(s2, sh);
    if (threadIdx.x == 0) {
        float m = s * (1.0f / 32768.0f);
        mean[c] = m;
        var[c] = s2 * (1.0f / 32768.0f) - m * m;
    }
}

__global__ void bn_silu(const float* __restrict__ y, const float* __restrict__ mean,
                        const float* __restrict__ var, const float* __restrict__ g,
                        const float* __restrict__ bta, float* __restrict__ out) {
    int idx = blockIdx.x * blockDim.x + threadIdx.x; // over B*512*HW
    int c = (idx >> 12) & 511;
    float v = (y[idx] - mean[c]) * rsqrtf(var[c] + 1e-5f) * g[c] + bta[c];
    out[idx] = v * sigmoidf_(v);
}

// ------------------------------- launcher -----------------------------------
static float* sym_addr(const void* symbol) {
    void* p = nullptr;
    cudaGetSymbolAddress(&p, symbol);
    return (float*)p;
}

extern "C" void kernel_launch(void* const* d_in, const int* in_sizes, int n_in,
                              void* d_out, int out_size) {
    const float* x       = (const float*)d_in[0];
    const float* box_w1  = (const float*)d_in[1];
    const float* box_b1  = (const float*)d_in[2];
    const float* box_w2  = (const float*)d_in[3];
    const float* box_b2  = (const float*)d_in[4];
    const float* edge_w1 = (const float*)d_in[5];
    const float* edge_b1 = (const float*)d_in[6];
    const float* gn_g    = (const float*)d_in[7];
    const float* gn_b    = (const float*)d_in[8];
    const float* edge_w2 = (const float*)d_in[9];
    const float* edge_b2 = (const float*)d_in[10];
    const float* qkv_w   = (const float*)d_in[11];
    const float* qkv_b   = (const float*)d_in[12];
    const float* fus_w   = (const float*)d_in[13];
    const float* fus_b   = (const float*)d_in[14];
    const float* bn_g    = (const float*)d_in[15];
    const float* bn_b    = (const float*)d_in[16];
    float* out = (float*)d_out;

    float* wt_box1  = sym_addr(g_wt_box1);
    float* wt_edge1 = sym_addr(g_wt_edge1);
    float* wt_qkv   = sym_addr(g_wt_qkv);
    float* wt_fus   = sym_addr(g_wt_fus);
    float* t1       = sym_addr(g_t1);
    float* boxes    = sym_addr(g_boxes);
    float* e1       = sym_addr(g_e1);
    float* edge     = sym_addr(g_edge);
    float* qkvbuf   = sym_addr(g_qkv);
    float* Sbuf     = sym_addr(g_S);
    float* fusin    = sym_addr(g_fusin);
    float* ybuf     = sym_addr(g_y);
    float* bnmean   = sym_addr(g_bnmean);
    float* bnvar    = sym_addr(g_bnvar);

    dim3 tb(32, 32);
    transpose_w<<<dim3(144, 2), tb>>>(box_w1, wt_box1, 64, 4608);
    transpose_w<<<dim3(2, 2), tb>>>(edge_w1, wt_edge1, 64, 36);
    transpose_w<<<dim3(16, 48), tb>>>(qkv_w, wt_qkv, 1536, 512);
    transpose_w<<<dim3(288, 16), tb>>>(fus_w, wt_fus, 512, 9216);

    // box_net
    conv_kernel<64, 128, 16, 4, 8, 3><<<dim3(256, 1), 256>>>(
        x, wt_box1, box_b1, t1, 512, 64, /*act=gelu*/1);
    conv1x1_small<4, 64><<<128, 256>>>(t1, box_w2, box_b2, boxes, /*sigmoid*/2);

    // edge_net
    conv_kernel<64, 128, 16, 4, 8, 3><<<dim3(256, 1), 256>>>(
        boxes, wt_edge1, edge_b1, e1, 4, 64, /*none*/0);
    groupnorm_gelu<<<64, 256>>>(e1, gn_g, gn_b);
    conv1x1_small<8, 64><<<128, 256>>>(e1, edge_w2, edge_b2, edge, /*none*/0);

    // qkv 1x1 conv
    conv_kernel<128, 128, 16, 8, 8, 1><<<dim3(256, 12), 256>>>(
        x, wt_qkv, qkv_b, qkvbuf, 512, 1536, 0);

    // attention
    qk_kernel<<<4096, 256>>>(qkvbuf, edge, Sbuf);
    softmax_i<<<1024, 256>>>(Sbuf);
    av_kernel<<<4096, 256>>>(Sbuf, qkvbuf, fusin);
    copy_x<<<16384, 256>>>(x, fusin);

    // fusion conv + BN + SiLU
    conv_kernel<128, 128, 16, 8, 8, 3><<<dim3(256, 4), 256>>>(
        fusin, wt_fus, fus_b, ybuf, 1024, 512, 0);
    bn_stats<<<512, 256>>>(ybuf, bnmean, bnvar);
    bn_silu<<<65536, 256>>>(ybuf, bnmean, bnvar, bn_g, bn_b, out);
}